// round 3
// baseline (speedup 1.0000x reference)
#include <cuda_runtime.h>
#include <float.h>

#define DIM    256
#define BSEG   256
#define CHUNK  40
#define PITCH  260   // floats per row in SMEM (260 % 4 == 0, odd/32 -> conflict-free patterns)

// ---------------- scratch (static device allocations; no cudaMalloc) ----------------
__device__ float qsG[DIM];            // scaled q (256)
__device__ float qkPartG[16 * DIM];   // 16 partial qk contributions, [part*4+h][d]
__device__ float sbiasPartG[16];      // partial score-bias contributions
__device__ float SnG[BSEG * 4 * DIM]; // normalized weighted sums, [b][h][d]
__device__ float pooledG[BSEG * DIM];
__device__ float attnG[BSEG * DIM];

// ---------------- P1: q = ((gq @ Wq^T) + bq) * (1/sqrt(64)) ----------------
__global__ __launch_bounds__(256) void prologue_q(const float* __restrict__ ipw,
                                                  const float* __restrict__ ipb,
                                                  const float* __restrict__ gq) {
    __shared__ float gqs[DIM];
    int t = threadIdx.x;
    gqs[t] = gq[t];
    __syncthreads();
    int w = t >> 5, l = t & 31;
    int row = blockIdx.x * 8 + w;   // 32 blocks * 8 warps = 256 rows
    float sum = 0.f;
#pragma unroll
    for (int k = l; k < DIM; k += 32) sum += ipw[row * DIM + k] * gqs[k];
#pragma unroll
    for (int off = 16; off; off >>= 1) sum += __shfl_xor_sync(0xffffffffu, sum, off);
    if (l == 0) qsG[row] = (sum + ipb[row]) * 0.125f;
}

// ---------------- P2: qk[h][d] = sum_j qs[h*64+j] * Wk[h*64+j][d]  (j split 4 ways) ----
__global__ __launch_bounds__(256) void prologue_qk(const float* __restrict__ ipw,
                                                   const float* __restrict__ ipb) {
    int bl = blockIdx.x;          // 16 blocks
    int h = bl >> 2, part = bl & 3;
    int j0 = h * 64 + part * 16;
    __shared__ float qsl[16];
    int t = threadIdx.x;
    if (t < 16) qsl[t] = qsG[j0 + t];
    __syncthreads();
    float a = 0.f;
#pragma unroll
    for (int jj = 0; jj < 16; jj++)
        a += qsl[jj] * ipw[(DIM + j0 + jj) * DIM + t];
    qkPartG[((part * 4 + h) << 8) + t] = a;
    if (t == 0) {
        float s = 0.f;
#pragma unroll
        for (int jj = 0; jj < 16; jj++) s += qsl[jj] * ipb[DIM + j0 + jj];
        sbiasPartG[part * 4 + h] = s;
    }
}

// ---------------- main: per-segment online softmax + weighted feature sum ------------
__global__ __launch_bounds__(256) void seg_kernel(const float* __restrict__ X,
                                                  const int* __restrict__ seg, int N) {
    __shared__ __align__(16) float Xs[CHUNK * PITCH];
    __shared__ float4 qkT4s[DIM];          // (qk0[d], qk1[d], qk2[d], qk3[d])
    __shared__ float4 es4[CHUNK];
    __shared__ float4 pm[2], pe[2];
    __shared__ __align__(16) float m_s[4], d_s[4], sbias_s[4];
    __shared__ int segLoHi[2];

    int t = threadIdx.x;
    int b = blockIdx.x;

    { // assemble qkT into smem (sum of 4 deterministic partials)
        float4 q;
        float* qp = (float*)&q;
#pragma unroll
        for (int h = 0; h < 4; h++) {
            float v = 0.f;
#pragma unroll
            for (int p = 0; p < 4; p++) v += qkPartG[((p * 4 + h) << 8) + t];
            qp[h] = v;
        }
        qkT4s[t] = q;
    }
    if (t < 4) {
        float s = 0.f;
#pragma unroll
        for (int p = 0; p < 4; p++) s += sbiasPartG[p * 4 + t];
        sbias_s[t] = s;
        m_s[t] = -FLT_MAX;
        d_s[t] = 0.f;
    }
    if (t == 0) {
        int lo = 0, hi = N;
        while (lo < hi) { int mid = (lo + hi) >> 1; if (seg[mid] < b) lo = mid + 1; else hi = mid; }
        segLoHi[0] = lo;
        int lo2 = lo, hi2 = N;
        while (lo2 < hi2) { int mid = (lo2 + hi2) >> 1; if (seg[mid] < b + 1) lo2 = mid + 1; else hi2 = mid; }
        segLoHi[1] = lo2;
    }
    __syncthreads();

    float4 sb = *(const float4*)sbias_s;
    float4 acc = make_float4(0.f, 0.f, 0.f, 0.f);
    int lo = segLoHi[0], hi = segLoHi[1];

    for (int base = lo; base < hi; base += CHUNK) {
        int C = min(CHUNK, hi - base);
        // ---- load chunk (coalesced float4) ----
        const float4* Xg = (const float4*)X + (size_t)base * 64;
        for (int idx = t; idx < C * 64; idx += 256) {
            int node = idx >> 6, dq = idx & 63;
            float4 v = Xg[idx];
            *(float4*)(Xs + node * PITCH + dq * 4) = v;
        }
        __syncthreads();

        // ---- scores for C nodes (lanes 0..63 active) + chunk max ----
        float4 s;
        if (t < 64) {
            if (t < C) {
                s = sb;
                const float4* xr = (const float4*)(Xs + t * PITCH);
#pragma unroll 16
                for (int i = 0; i < 64; i++) {
                    float4 x4 = xr[i];
                    float4 q0 = qkT4s[4 * i + 0], q1 = qkT4s[4 * i + 1];
                    float4 q2 = qkT4s[4 * i + 2], q3 = qkT4s[4 * i + 3];
                    s.x += x4.x * q0.x + x4.y * q1.x + x4.z * q2.x + x4.w * q3.x;
                    s.y += x4.x * q0.y + x4.y * q1.y + x4.z * q2.y + x4.w * q3.y;
                    s.z += x4.x * q0.z + x4.y * q1.z + x4.z * q2.z + x4.w * q3.z;
                    s.w += x4.x * q0.w + x4.y * q1.w + x4.z * q2.w + x4.w * q3.w;
                }
            } else {
                s = make_float4(-FLT_MAX, -FLT_MAX, -FLT_MAX, -FLT_MAX);
            }
            float4 r = s;
#pragma unroll
            for (int off = 16; off; off >>= 1) {
                r.x = fmaxf(r.x, __shfl_xor_sync(0xffffffffu, r.x, off));
                r.y = fmaxf(r.y, __shfl_xor_sync(0xffffffffu, r.y, off));
                r.z = fmaxf(r.z, __shfl_xor_sync(0xffffffffu, r.z, off));
                r.w = fmaxf(r.w, __shfl_xor_sync(0xffffffffu, r.w, off));
            }
            if ((t & 31) == 0) pm[t >> 5] = r;
        }
        __syncthreads();

        // ---- everyone: new max, rescale accumulators ----
        float4 mo = *(const float4*)m_s;
        float4 p0 = pm[0], p1 = pm[1];
        float4 nm;
        nm.x = fmaxf(mo.x, fmaxf(p0.x, p1.x));
        nm.y = fmaxf(mo.y, fmaxf(p0.y, p1.y));
        nm.z = fmaxf(mo.z, fmaxf(p0.z, p1.z));
        nm.w = fmaxf(mo.w, fmaxf(p0.w, p1.w));
        acc.x *= __expf(mo.x - nm.x);
        acc.y *= __expf(mo.y - nm.y);
        acc.z *= __expf(mo.z - nm.z);
        acc.w *= __expf(mo.w - nm.w);

        // ---- e + chunk sum (lanes 0..63) ----
        if (t < 64) {
            float4 e;
            if (t < C) {
                e.x = __expf(s.x - nm.x);
                e.y = __expf(s.y - nm.y);
                e.z = __expf(s.z - nm.z);
                e.w = __expf(s.w - nm.w);
                es4[t] = e;
            } else {
                e = make_float4(0.f, 0.f, 0.f, 0.f);
            }
            float4 r = e;
#pragma unroll
            for (int off = 16; off; off >>= 1) {
                r.x += __shfl_xor_sync(0xffffffffu, r.x, off);
                r.y += __shfl_xor_sync(0xffffffffu, r.y, off);
                r.z += __shfl_xor_sync(0xffffffffu, r.z, off);
                r.w += __shfl_xor_sync(0xffffffffu, r.w, off);
            }
            if ((t & 31) == 0) pe[t >> 5] = r;
        }
        __syncthreads();

        if (t < 4) { // update running m, denom
            float mo_t = m_s[t];
            float p = fmaxf(((const float*)&pm[0])[t], ((const float*)&pm[1])[t]);
            float nmt = fmaxf(mo_t, p);
            d_s[t] = d_s[t] * __expf(mo_t - nmt) + ((const float*)&pe[0])[t] + ((const float*)&pe[1])[t];
            m_s[t] = nmt;
        }

        // ---- rank-C update: acc[h] += e[n][h] * X[n][d=t] ----
#pragma unroll 4
        for (int n = 0; n < C; n++) {
            float4 e4 = es4[n];
            float xv = Xs[n * PITCH + t];
            acc.x += e4.x * xv;
            acc.y += e4.y * xv;
            acc.z += e4.z * xv;
            acc.w += e4.w * xv;
        }
        __syncthreads();
    }

    float4 dd = *(const float4*)d_s;
    float i0 = dd.x > 0.f ? 1.f / dd.x : 0.f;
    float i1 = dd.y > 0.f ? 1.f / dd.y : 0.f;
    float i2 = dd.z > 0.f ? 1.f / dd.z : 0.f;
    float i3 = dd.w > 0.f ? 1.f / dd.w : 0.f;
    float* Sp = SnG + b * (4 * DIM);
    Sp[0 * DIM + t] = acc.x * i0;
    Sp[1 * DIM + t] = acc.y * i1;
    Sp[2 * DIM + t] = acc.z * i2;
    Sp[3 * DIM + t] = acc.w * i3;
}

// ---------------- generic tiny tiled GEMM: C = A @ W^T + bias ------------------------
// mode 0: pooled = Sn(head-sliced) @ Wv^T + bv   (A row = SnG[b][head], head = n-tile)
// mode 1: attn   = pooled @ Wo^T + opb
// mode 2: out    = attn @ Ww^T + ob  -> d_out
__global__ __launch_bounds__(256) void gemm_kernel(int mode,
                                                   const float* __restrict__ Wt,
                                                   const float* __restrict__ bias,
                                                   float* __restrict__ outp,
                                                   int Ncols) {
    const float* A; int lda, hstride; float* Cc;
    if (mode == 0)      { A = SnG;     lda = 1024; hstride = 256; Cc = pooledG; }
    else if (mode == 1) { A = pooledG; lda = 256;  hstride = 0;   Cc = attnG;  }
    else                { A = attnG;   lda = 256;  hstride = 0;   Cc = outp;   }
    const int K = 256;
    __shared__ float As[16 * 65];
    __shared__ float Ws[16 * 65];
    int t = threadIdx.x;
    int tx = t & 15, ty = t >> 4;
    int nBase = blockIdx.x * 64, mBase = blockIdx.y * 64;
    int hOff = blockIdx.x * hstride;
    float c[4][4] = {};
    for (int k0 = 0; k0 < K; k0 += 16) {
#pragma unroll
        for (int r = 0; r < 4; r++) {
            int i = t + r * 256;
            int kk = i & 15, mm = i >> 4;
            As[kk * 65 + mm] = A[(mBase + mm) * lda + hOff + k0 + kk];
            Ws[kk * 65 + mm] = Wt[(nBase + mm) * K + k0 + kk];
        }
        __syncthreads();
#pragma unroll
        for (int kk = 0; kk < 16; kk++) {
            float a0 = As[kk * 65 + ty * 4 + 0];
            float a1 = As[kk * 65 + ty * 4 + 1];
            float a2 = As[kk * 65 + ty * 4 + 2];
            float a3 = As[kk * 65 + ty * 4 + 3];
            float w0 = Ws[kk * 65 + tx * 4 + 0];
            float w1 = Ws[kk * 65 + tx * 4 + 1];
            float w2 = Ws[kk * 65 + tx * 4 + 2];
            float w3 = Ws[kk * 65 + tx * 4 + 3];
            c[0][0] += a0 * w0; c[0][1] += a0 * w1; c[0][2] += a0 * w2; c[0][3] += a0 * w3;
            c[1][0] += a1 * w0; c[1][1] += a1 * w1; c[1][2] += a1 * w2; c[1][3] += a1 * w3;
            c[2][0] += a2 * w0; c[2][1] += a2 * w1; c[2][2] += a2 * w2; c[2][3] += a2 * w3;
            c[3][0] += a3 * w0; c[3][1] += a3 * w1; c[3][2] += a3 * w2; c[3][3] += a3 * w3;
        }
        __syncthreads();
    }
#pragma unroll
    for (int i2 = 0; i2 < 4; i2++) {
        int row = mBase + ty * 4 + i2;
#pragma unroll
        for (int j2 = 0; j2 < 4; j2++) {
            int col = nBase + tx * 4 + j2;
            Cc[row * Ncols + col] = c[i2][j2] + bias[col];
        }
    }
}

// ---------------- launch (R2 resubmit: broker infra failed twice; design unchanged) ----
extern "C" void kernel_launch(void* const* d_in, const int* in_sizes, int n_in,
                              void* d_out, int out_size) {
    const float* node_feat = (const float*)d_in[0];
    const int*   segids    = (const int*)d_in[1];
    const float* gq        = (const float*)d_in[2];
    const float* ipw       = (const float*)d_in[3];
    const float* ipb       = (const float*)d_in[4];
    const float* opw       = (const float*)d_in[5];
    const float* opb       = (const float*)d_in[6];
    const float* ow        = (const float*)d_in[7];
    const float* ob        = (const float*)d_in[8];
    int N = in_sizes[0] / DIM;
    float* out = (float*)d_out;

    prologue_q<<<32, 256>>>(ipw, ipb, gq);
    prologue_qk<<<16, 256>>>(ipw, ipb);
    seg_kernel<<<BSEG, 256>>>(node_feat, segids, N);
    gemm_kernel<<<dim3(4, 4), 256>>>(0, ipw + 512 * 256, ipb + 512, out, 256);
    gemm_kernel<<<dim3(4, 4), 256>>>(1, opw, opb, out, 256);
    gemm_kernel<<<dim3(8, 4), 256>>>(2, ow, ob, out, 512);
}

// round 4
// speedup vs baseline: 1.4630x; 1.4630x over previous
#include <cuda_runtime.h>
#include <float.h>

#define DIM    256
#define BSEG   256
#define CHUNK  36
#define KREG   9     // CHUNK*64/256 float4 loads per thread
#define PITCH  260   // floats per SMEM row; 1040B stride => conflict-free LDS.128 column pattern

// ---------------- scratch (static device arrays; no cudaMalloc) ----------------
__device__ float qsG[DIM];
__device__ float qkPartG[16 * DIM];
__device__ float sbiasPartG[16];
__device__ float SnG[BSEG * 4 * DIM]; // normalized weighted sums, [b][h][d]
__device__ float pooledG[BSEG * DIM];
__device__ float attnG[BSEG * DIM];

// ---------------- P1: q = ((gq @ Wq^T) + bq) * (1/sqrt(64)) ----------------
__global__ __launch_bounds__(256) void prologue_q(const float* __restrict__ ipw,
                                                  const float* __restrict__ ipb,
                                                  const float* __restrict__ gq) {
    __shared__ float gqs[DIM];
    int t = threadIdx.x;
    gqs[t] = gq[t];
    __syncthreads();
    int w = t >> 5, l = t & 31;
    int row = blockIdx.x * 8 + w;
    float sum = 0.f;
#pragma unroll
    for (int k = l; k < DIM; k += 32) sum += ipw[row * DIM + k] * gqs[k];
#pragma unroll
    for (int off = 16; off; off >>= 1) sum += __shfl_xor_sync(0xffffffffu, sum, off);
    if (l == 0) qsG[row] = (sum + ipb[row]) * 0.125f;
}

// ---------------- P2: qk[h][d] = sum_j qs[h*64+j] * Wk[h*64+j][d] ----------------
__global__ __launch_bounds__(256) void prologue_qk(const float* __restrict__ ipw,
                                                   const float* __restrict__ ipb) {
    int bl = blockIdx.x;          // 16 blocks
    int h = bl >> 2, part = bl & 3;
    int j0 = h * 64 + part * 16;
    __shared__ float qsl[16];
    int t = threadIdx.x;
    if (t < 16) qsl[t] = qsG[j0 + t];
    __syncthreads();
    float a = 0.f;
#pragma unroll
    for (int jj = 0; jj < 16; jj++)
        a += qsl[jj] * ipw[(DIM + j0 + jj) * DIM + t];
    qkPartG[((part * 4 + h) << 8) + t] = a;
    if (t == 0) {
        float s = 0.f;
#pragma unroll
        for (int jj = 0; jj < 16; jj++) s += qsl[jj] * ipb[DIM + j0 + jj];
        sbiasPartG[part * 4 + h] = s;
    }
}

// ---------------- main: per-segment online softmax + weighted feature sum ------------
__global__ __launch_bounds__(256, 2) void seg_kernel(const float* __restrict__ X,
                                                     const int* __restrict__ seg, int N) {
    __shared__ __align__(16) float Xs[CHUNK * PITCH];   // 37.44 KB
    __shared__ float4 qkT4s[DIM];                       // 4 KB
    __shared__ float4 sp[4][CHUNK];                     // 2.3 KB score partials (D-quarters)
    __shared__ float4 es4[CHUNK];
    __shared__ float4 pm[2], pe[2];
    __shared__ __align__(16) float m_s[4], d_s[4], sbias_s[4];
    __shared__ int segLoHi[2];

    int t = threadIdx.x;
    int b = blockIdx.x;

    { // assemble qkT (sum of 4 deterministic partials)
        float4 q;
        float* qp = (float*)&q;
#pragma unroll
        for (int h = 0; h < 4; h++) {
            float v = 0.f;
#pragma unroll
            for (int p = 0; p < 4; p++) v += qkPartG[((p * 4 + h) << 8) + t];
            qp[h] = v;
        }
        qkT4s[t] = q;
    }
    if (t < 4) {
        float s = 0.f;
#pragma unroll
        for (int p = 0; p < 4; p++) s += sbiasPartG[p * 4 + t];
        sbias_s[t] = s;
        m_s[t] = -FLT_MAX;
        d_s[t] = 0.f;
    }
    if (t == 0) {
        int lo = 0, hi = N;
        while (lo < hi) { int mid = (lo + hi) >> 1; if (seg[mid] < b) lo = mid + 1; else hi = mid; }
        segLoHi[0] = lo;
        int lo2 = lo, hi2 = N;
        while (lo2 < hi2) { int mid = (lo2 + hi2) >> 1; if (seg[mid] < b + 1) lo2 = mid + 1; else hi2 = mid; }
        segLoHi[1] = lo2;
    }
    __syncthreads();

    float4 sb = *(const float4*)sbias_s;
    float4 acc = make_float4(0.f, 0.f, 0.f, 0.f);
    int lo = segLoHi[0], hi = segLoHi[1];

    // ---- register-staged prefetch pipeline ----
    float4 R[KREG];
    int base = lo;
    int C = (hi > lo) ? min(CHUNK, hi - lo) : 0;
    if (C > 0) {
        const float4* Xg = (const float4*)X + (size_t)base * 64;
#pragma unroll
        for (int k = 0; k < KREG; k++) {
            int idx = t + (k << 8);
            if (idx < C * 64) R[k] = Xg[idx];
        }
    }

    while (base < hi) {
        // ---- store staged chunk to SMEM ----
#pragma unroll
        for (int k = 0; k < KREG; k++) {
            int idx = t + (k << 8);
            if (idx < C * 64) {
                int node = idx >> 6, dq = idx & 63;
                *(float4*)(Xs + node * PITCH + dq * 4) = R[k];
            }
        }
        // ---- kick prefetch of next chunk (latency hidden behind phases below) ----
        int baseN = base + CHUNK;
        int CN = 0;
        if (baseN < hi) {
            CN = min(CHUNK, hi - baseN);
            const float4* Xg2 = (const float4*)X + (size_t)baseN * 64;
#pragma unroll
            for (int k = 0; k < KREG; k++) {
                int idx = t + (k << 8);
                if (idx < CN * 64) R[k] = Xg2[idx];
            }
        }
        __syncthreads();   // Xs ready

        // ---- score partials: all 8 warps; quarter p covers i in [16p, 16p+16) ----
        {
            int p = t >> 6, n = t & 63;
            if (n < CHUNK) {
                float4 s = make_float4(0.f, 0.f, 0.f, 0.f);
                const float4* xr = (const float4*)(Xs + n * PITCH) + 16 * p;
                const float4* qb = qkT4s + 64 * p;
#pragma unroll
                for (int i = 0; i < 16; i++) {
                    float4 x4 = xr[i];
                    float4 q0 = qb[4 * i + 0], q1 = qb[4 * i + 1];
                    float4 q2 = qb[4 * i + 2], q3 = qb[4 * i + 3];
                    s.x += x4.x * q0.x + x4.y * q1.x + x4.z * q2.x + x4.w * q3.x;
                    s.y += x4.x * q0.y + x4.y * q1.y + x4.z * q2.y + x4.w * q3.y;
                    s.z += x4.x * q0.z + x4.y * q1.z + x4.z * q2.z + x4.w * q3.z;
                    s.w += x4.x * q0.w + x4.y * q1.w + x4.z * q2.w + x4.w * q3.w;
                }
                sp[p][n] = s;
            }
        }
        __syncthreads();   // partials ready

        // ---- combine + chunk max (lanes 0..63) ----
        float4 s;
        if (t < 64) {
            if (t < C) {
                float4 a0 = sp[0][t], a1 = sp[1][t], a2 = sp[2][t], a3 = sp[3][t];
                s.x = sb.x + a0.x + a1.x + a2.x + a3.x;
                s.y = sb.y + a0.y + a1.y + a2.y + a3.y;
                s.z = sb.z + a0.z + a1.z + a2.z + a3.z;
                s.w = sb.w + a0.w + a1.w + a2.w + a3.w;
            } else {
                s = make_float4(-FLT_MAX, -FLT_MAX, -FLT_MAX, -FLT_MAX);
            }
            float4 r = s;
#pragma unroll
            for (int off = 16; off; off >>= 1) {
                r.x = fmaxf(r.x, __shfl_xor_sync(0xffffffffu, r.x, off));
                r.y = fmaxf(r.y, __shfl_xor_sync(0xffffffffu, r.y, off));
                r.z = fmaxf(r.z, __shfl_xor_sync(0xffffffffu, r.z, off));
                r.w = fmaxf(r.w, __shfl_xor_sync(0xffffffffu, r.w, off));
            }
            if ((t & 31) == 0) pm[t >> 5] = r;
        }
        __syncthreads();

        // ---- everyone: new max, rescale accumulators ----
        float4 mo = *(const float4*)m_s;
        float4 p0 = pm[0], p1 = pm[1];
        float4 nm;
        nm.x = fmaxf(mo.x, fmaxf(p0.x, p1.x));
        nm.y = fmaxf(mo.y, fmaxf(p0.y, p1.y));
        nm.z = fmaxf(mo.z, fmaxf(p0.z, p1.z));
        nm.w = fmaxf(mo.w, fmaxf(p0.w, p1.w));
        acc.x *= __expf(mo.x - nm.x);
        acc.y *= __expf(mo.y - nm.y);
        acc.z *= __expf(mo.z - nm.z);
        acc.w *= __expf(mo.w - nm.w);

        // ---- e + chunk sum (lanes 0..63, s still live) ----
        if (t < 64) {
            float4 e;
            if (t < C) {
                e.x = __expf(s.x - nm.x);
                e.y = __expf(s.y - nm.y);
                e.z = __expf(s.z - nm.z);
                e.w = __expf(s.w - nm.w);
                es4[t] = e;
            } else {
                e = make_float4(0.f, 0.f, 0.f, 0.f);
            }
            float4 r = e;
#pragma unroll
            for (int off = 16; off; off >>= 1) {
                r.x += __shfl_xor_sync(0xffffffffu, r.x, off);
                r.y += __shfl_xor_sync(0xffffffffu, r.y, off);
                r.z += __shfl_xor_sync(0xffffffffu, r.z, off);
                r.w += __shfl_xor_sync(0xffffffffu, r.w, off);
            }
            if ((t & 31) == 0) pe[t >> 5] = r;
        }
        __syncthreads();

        if (t < 4) { // running m, denom
            float mo_t = m_s[t];
            float p = fmaxf(((const float*)&pm[0])[t], ((const float*)&pm[1])[t]);
            float nmt = fmaxf(mo_t, p);
            d_s[t] = d_s[t] * __expf(mo_t - nmt) + ((const float*)&pe[0])[t] + ((const float*)&pe[1])[t];
            m_s[t] = nmt;
        }

        // ---- rank-C update: acc[h] += e[n][h] * X[n][d=t] ----
#pragma unroll 4
        for (int n = 0; n < C; n++) {
            float4 e4 = es4[n];
            float xv = Xs[n * PITCH + t];
            acc.x += e4.x * xv;
            acc.y += e4.y * xv;
            acc.z += e4.z * xv;
            acc.w += e4.w * xv;
        }
        __syncthreads();   // protect Xs/es4 before next chunk's store

        base = baseN;
        C = CN;
    }

    float4 dd = *(const float4*)d_s;
    float i0 = dd.x > 0.f ? 1.f / dd.x : 0.f;
    float i1 = dd.y > 0.f ? 1.f / dd.y : 0.f;
    float i2 = dd.z > 0.f ? 1.f / dd.z : 0.f;
    float i3 = dd.w > 0.f ? 1.f / dd.w : 0.f;
    float* Sp = SnG + b * (4 * DIM);
    Sp[0 * DIM + t] = acc.x * i0;
    Sp[1 * DIM + t] = acc.y * i1;
    Sp[2 * DIM + t] = acc.z * i2;
    Sp[3 * DIM + t] = acc.w * i3;
}

// ---------------- tiny GEMM: C = A @ W^T + bias,  BM=64 BN=16 KT=32 -------------------
// mode 0: pooled = Sn(head-sliced) @ Wv^T + bv
// mode 1: attn   = pooled @ Wo^T + opb
// mode 2: out    = attn @ Ww^T + ob  -> d_out
__global__ __launch_bounds__(256) void gemm_kernel(int mode,
                                                   const float* __restrict__ Wt,
                                                   const float* __restrict__ bias,
                                                   float* __restrict__ outp,
                                                   int Ncols) {
    const float* A; int lda, hstride; float* Cc;
    if (mode == 0)      { A = SnG;     lda = 1024; hstride = 256; Cc = pooledG; }
    else if (mode == 1) { A = pooledG; lda = 256;  hstride = 0;   Cc = attnG;  }
    else                { A = attnG;   lda = 256;  hstride = 0;   Cc = outp;   }
    const int K = 256;
    __shared__ __align__(16) float As[32 * 68];  // [kk][m], pad 68 keeps 16B alignment
    __shared__ float Ws[32 * 17];                // [kk][n]
    int t = threadIdx.x;
    int c = t & 15, rg = t >> 4;                 // col, row-group (4 rows each)
    int nBase = blockIdx.x * 16, mBase = blockIdx.y * 64;
    int hOff = (nBase >> 6) * hstride;
    float acc0 = 0.f, acc1 = 0.f, acc2 = 0.f, acc3 = 0.f;

    for (int k0 = 0; k0 < K; k0 += 32) {
        // load A tile: 64 rows x 32 k = 512 float4, 2 per thread
#pragma unroll
        for (int r = 0; r < 2; r++) {
            int f = t + r * 256;
            int m = f >> 3, kg = f & 7;
            float4 av = *(const float4*)(A + (size_t)(mBase + m) * lda + hOff + k0 + 4 * kg);
            As[(4 * kg + 0) * 68 + m] = av.x;
            As[(4 * kg + 1) * 68 + m] = av.y;
            As[(4 * kg + 2) * 68 + m] = av.z;
            As[(4 * kg + 3) * 68 + m] = av.w;
        }
        // load W tile: 16 rows x 32 k = 128 float4
        if (t < 128) {
            int n = t >> 3, kg = t & 7;
            float4 wv = *(const float4*)(Wt + (size_t)(nBase + n) * K + k0 + 4 * kg);
            Ws[(4 * kg + 0) * 17 + n] = wv.x;
            Ws[(4 * kg + 1) * 17 + n] = wv.y;
            Ws[(4 * kg + 2) * 17 + n] = wv.z;
            Ws[(4 * kg + 3) * 17 + n] = wv.w;
        }
        __syncthreads();
#pragma unroll
        for (int kk = 0; kk < 32; kk++) {
            float4 a4 = *(const float4*)(As + kk * 68 + 4 * rg);  // broadcast within warp
            float w = Ws[kk * 17 + c];
            acc0 += a4.x * w;
            acc1 += a4.y * w;
            acc2 += a4.z * w;
            acc3 += a4.w * w;
        }
        __syncthreads();
    }
    float bv = bias[nBase + c];
    int col = nBase + c;
    Cc[(size_t)(mBase + 4 * rg + 0) * Ncols + col] = acc0 + bv;
    Cc[(size_t)(mBase + 4 * rg + 1) * Ncols + col] = acc1 + bv;
    Cc[(size_t)(mBase + 4 * rg + 2) * Ncols + col] = acc2 + bv;
    Cc[(size_t)(mBase + 4 * rg + 3) * Ncols + col] = acc3 + bv;
}

// ---------------- launch -------------------------------------------------------------
extern "C" void kernel_launch(void* const* d_in, const int* in_sizes, int n_in,
                              void* d_out, int out_size) {
    const float* node_feat = (const float*)d_in[0];
    const int*   segids    = (const int*)d_in[1];
    const float* gq        = (const float*)d_in[2];
    const float* ipw       = (const float*)d_in[3];
    const float* ipb       = (const float*)d_in[4];
    const float* opw       = (const float*)d_in[5];
    const float* opb       = (const float*)d_in[6];
    const float* ow        = (const float*)d_in[7];
    const float* ob        = (const float*)d_in[8];
    int N = in_sizes[0] / DIM;
    float* out = (float*)d_out;

    prologue_q<<<32, 256>>>(ipw, ipb, gq);
    prologue_qk<<<16, 256>>>(ipw, ipb);
    seg_kernel<<<BSEG, 256>>>(node_feat, segids, N);
    gemm_kernel<<<dim3(16, 4), 256>>>(0, ipw + 512 * 256, ipb + 512, out, 256);
    gemm_kernel<<<dim3(16, 4), 256>>>(1, opw, opb, out, 256);
    gemm_kernel<<<dim3(32, 4), 256>>>(2, ow, ob, out, 512);
}

// round 5
// speedup vs baseline: 1.5192x; 1.0385x over previous
#include <cuda_runtime.h>
#include <float.h>

#define DIM    256
#define BSEG   256
#define CHUNK  36
#define KREG   9     // CHUNK*64/256 float4 loads per thread
#define PITCH  260   // floats per SMEM row; 1040B stride -> conflict-free LDS.128 patterns

// ---------------- scratch (static device arrays; no cudaMalloc) ----------------
__device__ float qsG[DIM];                  // scaled q
__device__ float qkGf[4 * DIM];             // final qk, [d][h] interleaved (float4 per d)
__device__ float accPartG[2 * BSEG * 1024]; // raw per-half sums, [b*2+half][h*256+d]
__device__ float denomPartG[2 * BSEG * 4];  // raw per-half denoms, [b*2+half][h]
__device__ float pooledG[BSEG * DIM];
__device__ float attnG[BSEG * DIM];

// ---------------- P1: q = ((gq @ Wq^T) + bq) * (1/sqrt(64)) ----------------
__global__ __launch_bounds__(256) void prologue_q(const float* __restrict__ ipw,
                                                  const float* __restrict__ ipb,
                                                  const float* __restrict__ gq) {
    __shared__ float gqs[DIM];
    int t = threadIdx.x;
    gqs[t] = gq[t];
    __syncthreads();
    int w = t >> 5, l = t & 31;
    int row = blockIdx.x * 8 + w;
    float sum = 0.f;
#pragma unroll
    for (int k = l; k < DIM; k += 32) sum += ipw[row * DIM + k] * gqs[k];
#pragma unroll
    for (int off = 16; off; off >>= 1) sum += __shfl_xor_sync(0xffffffffu, sum, off);
    if (l == 0) qsG[row] = (sum + ipb[row]) * 0.125f;
}

// ---------------- P2: qk[h][d] = sum_{j<64} qs[h*64+j] * Wk[h*64+j][d] ----------------
// (score bias from bk cancels in softmax normalization -> not computed)
__global__ __launch_bounds__(256) void prologue_qk(const float* __restrict__ ipw) {
    int h = blockIdx.x;                 // 4 blocks
    __shared__ float qsl[64];
    int t = threadIdx.x;
    if (t < 64) qsl[t] = qsG[h * 64 + t];
    __syncthreads();
    const float* W = ipw + (size_t)(DIM + h * 64) * DIM;
    float a = 0.f;
#pragma unroll 16
    for (int j = 0; j < 64; j++) a += qsl[j] * W[j * DIM + t];
    qkGf[t * 4 + h] = a;
}

// ---------------- main: per-half-segment softmax-weighted feature sums ----------------
// No max subtraction (scores ~ N(0,1): exp safe; max cancels exactly in normalization).
// Partial sums are additive across halves; normalization happens in the mode-0 GEMM.
__global__ __launch_bounds__(256, 2) void seg_kernel(const float* __restrict__ X,
                                                     const int* __restrict__ seg, int N) {
    __shared__ __align__(16) float Xs[CHUNK * PITCH];   // 37.4 KB
    __shared__ float4 qkT4s[DIM];                       // 4 KB
    __shared__ float4 sp[4][CHUNK];                     // score partials (D-quarters)
    __shared__ float4 es4[CHUNK];
    __shared__ float4 pdacc[2];
    __shared__ int segLoHi[2];

    int t = threadIdx.x;
    int bid = blockIdx.x;
    int b = bid >> 1, half = bid & 1;

    qkT4s[t] = ((const float4*)qkGf)[t];
    if (t == 0) {
        int lo = 0, hi = N;
        while (lo < hi) { int mid = (lo + hi) >> 1; if (seg[mid] < b) lo = mid + 1; else hi = mid; }
        int lo2 = lo, hi2 = N;
        while (lo2 < hi2) { int mid = (lo2 + hi2) >> 1; if (seg[mid] < b + 1) lo2 = mid + 1; else hi2 = mid; }
        int cnt = hi2 - lo, lenA = (cnt + 1) >> 1;
        segLoHi[0] = half ? (lo + lenA) : lo;
        segLoHi[1] = half ? hi2 : (lo + lenA);
    }
    __syncthreads();

    float4 acc = make_float4(0.f, 0.f, 0.f, 0.f);
    float4 dacc = make_float4(0.f, 0.f, 0.f, 0.f);
    int lo = segLoHi[0], hi = segLoHi[1];

    // ---- register-staged prefetch pipeline ----
    float4 R[KREG];
    int base = lo;
    int C = (hi > lo) ? min(CHUNK, hi - lo) : 0;
    if (C > 0) {
        const float4* Xg = (const float4*)X + (size_t)base * 64;
#pragma unroll
        for (int k = 0; k < KREG; k++) {
            int idx = t + (k << 8);
            if (idx < C * 64) R[k] = Xg[idx];
        }
    }

    while (base < hi) {
        // ---- store staged chunk to SMEM ----
#pragma unroll
        for (int k = 0; k < KREG; k++) {
            int idx = t + (k << 8);
            if (idx < C * 64) {
                int node = idx >> 6, dq = idx & 63;
                *(float4*)(Xs + node * PITCH + dq * 4) = R[k];
            }
        }
        // ---- kick prefetch of next chunk ----
        int baseN = base + CHUNK;
        int CN = 0;
        if (baseN < hi) {
            CN = min(CHUNK, hi - baseN);
            const float4* Xg2 = (const float4*)X + (size_t)baseN * 64;
#pragma unroll
            for (int k = 0; k < KREG; k++) {
                int idx = t + (k << 8);
                if (idx < CN * 64) R[k] = Xg2[idx];
            }
        }
        __syncthreads();   // Xs ready

        // ---- score partials: all 8 warps; quarter p covers i in [16p,16p+16) ----
        {
            int p = t >> 6, n = t & 63;
            if (n < CHUNK) {
                float4 s = make_float4(0.f, 0.f, 0.f, 0.f);
                const float4* xr = (const float4*)(Xs + n * PITCH) + 16 * p;
                const float4* qb = qkT4s + 64 * p;
#pragma unroll
                for (int i = 0; i < 16; i++) {
                    float4 x4 = xr[i];
                    float4 q0 = qb[4 * i + 0], q1 = qb[4 * i + 1];
                    float4 q2 = qb[4 * i + 2], q3 = qb[4 * i + 3];
                    s.x += x4.x * q0.x + x4.y * q1.x + x4.z * q2.x + x4.w * q3.x;
                    s.y += x4.x * q0.y + x4.y * q1.y + x4.z * q2.y + x4.w * q3.y;
                    s.z += x4.x * q0.z + x4.y * q1.z + x4.z * q2.z + x4.w * q3.z;
                    s.w += x4.x * q0.w + x4.y * q1.w + x4.z * q2.w + x4.w * q3.w;
                }
                sp[p][n] = s;
            }
        }
        __syncthreads();   // partials ready

        // ---- combine + exp + denom (lanes 0..63; warp0: n 0-31, warp1: n 32-63) ----
        if (t < 64) {
            float4 e;
            if (t < C) {
                float4 a0 = sp[0][t], a1 = sp[1][t], a2 = sp[2][t], a3 = sp[3][t];
                e.x = __expf(a0.x + a1.x + a2.x + a3.x);
                e.y = __expf(a0.y + a1.y + a2.y + a3.y);
                e.z = __expf(a0.z + a1.z + a2.z + a3.z);
                e.w = __expf(a0.w + a1.w + a2.w + a3.w);
                es4[t] = e;
            } else {
                e = make_float4(0.f, 0.f, 0.f, 0.f);
            }
            float4 r = e;
#pragma unroll
            for (int off = 16; off; off >>= 1) {
                r.x += __shfl_xor_sync(0xffffffffu, r.x, off);
                r.y += __shfl_xor_sync(0xffffffffu, r.y, off);
                r.z += __shfl_xor_sync(0xffffffffu, r.z, off);
                r.w += __shfl_xor_sync(0xffffffffu, r.w, off);
            }
            dacc.x += r.x; dacc.y += r.y; dacc.z += r.z; dacc.w += r.w;
        }
        __syncthreads();   // es4 ready

        // ---- rank-C update: acc[h] += e[n][h] * X[n][d=t] ----
#pragma unroll 4
        for (int n = 0; n < C; n++) {
            float4 e4 = es4[n];
            float xv = Xs[n * PITCH + t];
            acc.x += e4.x * xv;
            acc.y += e4.y * xv;
            acc.z += e4.z * xv;
            acc.w += e4.w * xv;
        }
        __syncthreads();   // protect Xs/es4 before next chunk's store

        base = baseN;
        C = CN;
    }

    // ---- raw partial outputs (summed + normalized inside mode-0 GEMM) ----
    float* Ap = accPartG + (size_t)bid * 1024;
    Ap[0 * DIM + t] = acc.x;
    Ap[1 * DIM + t] = acc.y;
    Ap[2 * DIM + t] = acc.z;
    Ap[3 * DIM + t] = acc.w;
    if (t == 0)  pdacc[0] = dacc;
    if (t == 32) pdacc[1] = dacc;
    __syncthreads();
    if (t < 4) denomPartG[bid * 4 + t] = ((const float*)&pdacc[0])[t] + ((const float*)&pdacc[1])[t];
}

// ---------------- tiny GEMM: BM=8, BN=32, full K=256 in one SMEM phase ---------------
// mode 0: pooled = (accA+accB head-sliced)/denom @ Wv^T + bv
// mode 1: attn   = pooled @ Wo^T + opb
// mode 2: out    = attn @ Ww^T + ob  -> d_out
__global__ __launch_bounds__(256) void gemm_kernel(int mode,
                                                   const float* __restrict__ Wt,
                                                   const float* __restrict__ bias,
                                                   float* __restrict__ outp,
                                                   int Ncols) {
    __shared__ __align__(16) float As[8 * PITCH];    // 8.3 KB
    __shared__ __align__(16) float Ws[32 * PITCH];   // 33.3 KB
    int t = threadIdx.x;
    int r = t >> 5, c = t & 31;
    int nBase = blockIdx.x * 32, mBase = blockIdx.y * 8;

    // ---- load A tile (8 rows x 256 k = 512 float4; 2/thread) ----
    if (mode == 0) {
        int hOff4 = (nBase >> 6) * 64;
#pragma unroll
        for (int i = 0; i < 2; i++) {
            int f = t + (i << 8);
            int m = f >> 6, k4 = f & 63;
            const float4* p0 = (const float4*)accPartG + (size_t)(mBase + m) * 512 + hOff4 + k4;
            float4 a0 = p0[0];
            float4 a1 = p0[256];   // second half partial
            float4 s = make_float4(a0.x + a1.x, a0.y + a1.y, a0.z + a1.z, a0.w + a1.w);
            *(float4*)(As + m * PITCH + 4 * k4) = s;
        }
    } else {
        const float* A = (mode == 1) ? pooledG : attnG;
#pragma unroll
        for (int i = 0; i < 2; i++) {
            int f = t + (i << 8);
            int m = f >> 6, k4 = f & 63;
            float4 a = ((const float4*)A)[(size_t)(mBase + m) * 64 + k4];
            *(float4*)(As + m * PITCH + 4 * k4) = a;
        }
    }
    // ---- load W tile (32 rows x 256 k = 2048 float4; 8/thread) ----
#pragma unroll
    for (int i = 0; i < 8; i++) {
        int f = t + (i << 8);
        int n = f >> 6, k4 = f & 63;
        float4 w = ((const float4*)Wt)[(size_t)(nBase + n) * 64 + k4];
        *(float4*)(Ws + n * PITCH + 4 * k4) = w;
    }
    __syncthreads();

    float acc = 0.f;
#pragma unroll
    for (int k4 = 0; k4 < 64; k4++) {
        float4 a4 = *(const float4*)(As + r * PITCH + 4 * k4);  // broadcast within warp
        float4 w4 = *(const float4*)(Ws + c * PITCH + 4 * k4);  // conflict-free (pitch 260)
        acc += a4.x * w4.x + a4.y * w4.y + a4.z * w4.z + a4.w * w4.w;
    }

    int row = mBase + r, col = nBase + c;
    if (mode == 0) {
        int h = nBase >> 6;
        float d = denomPartG[(row * 2) * 4 + h] + denomPartG[(row * 2 + 1) * 4 + h];
        float inv = d > 0.f ? 1.f / d : 0.f;
        pooledG[row * DIM + col] = acc * inv + bias[col];
    } else if (mode == 1) {
        attnG[row * DIM + col] = acc + bias[col];
    } else {
        outp[(size_t)row * Ncols + col] = acc + bias[col];
    }
}

// ---------------- launch -------------------------------------------------------------
extern "C" void kernel_launch(void* const* d_in, const int* in_sizes, int n_in,
                              void* d_out, int out_size) {
    const float* node_feat = (const float*)d_in[0];
    const int*   segids    = (const int*)d_in[1];
    const float* gq        = (const float*)d_in[2];
    const float* ipw       = (const float*)d_in[3];
    const float* ipb       = (const float*)d_in[4];
    const float* opw       = (const float*)d_in[5];
    const float* opb       = (const float*)d_in[6];
    const float* ow        = (const float*)d_in[7];
    const float* ob        = (const float*)d_in[8];
    int N = in_sizes[0] / DIM;
    float* out = (float*)d_out;

    prologue_q<<<32, 256>>>(ipw, ipb, gq);
    prologue_qk<<<4, 256>>>(ipw);
    seg_kernel<<<2 * BSEG, 256>>>(node_feat, segids, N);
    gemm_kernel<<<dim3(8, 32), 256>>>(0, ipw + 512 * 256, ipb + 512, out, 256);
    gemm_kernel<<<dim3(8, 32), 256>>>(1, opw, opb, out, 256);
    gemm_kernel<<<dim3(16, 32), 256>>>(2, ow, ob, out, 512);
}

// round 6
// speedup vs baseline: 1.5443x; 1.0165x over previous
#include <cuda_runtime.h>
#include <float.h>

#define DIM    256
#define BSEG   256
#define NSPLIT 4
#define CHUNK  32
#define PITCH  260   // floats per SMEM row; conflict-free LDS patterns

// ---------------- scratch (static device arrays; no cudaMalloc) ----------------
__device__ float qsG[DIM];                        // scaled q
__device__ float qkGf[4 * DIM];                   // final qk, [d][h] interleaved
__device__ float accPartG[NSPLIT * BSEG * 1024];  // raw per-quarter sums, [b*4+q][h*256+d]
__device__ float denomPartG[NSPLIT * BSEG * 4];   // raw per-quarter denoms, [b*4+q][h]
__device__ float pooledG[BSEG * DIM];
__device__ float attnG[BSEG * DIM];

// ---------------- P1: q = ((gq @ Wq^T) + bq) * (1/sqrt(64)) ----------------
__global__ __launch_bounds__(256) void prologue_q(const float* __restrict__ ipw,
                                                  const float* __restrict__ ipb,
                                                  const float* __restrict__ gq) {
    __shared__ float gqs[DIM];
    int t = threadIdx.x;
    gqs[t] = gq[t];
    __syncthreads();
    int w = t >> 5, l = t & 31;
    int row = blockIdx.x * 8 + w;
    float sum = 0.f;
#pragma unroll
    for (int k = l; k < DIM; k += 32) sum += ipw[row * DIM + k] * gqs[k];
#pragma unroll
    for (int off = 16; off; off >>= 1) sum += __shfl_xor_sync(0xffffffffu, sum, off);
    if (l == 0) qsG[row] = (sum + ipb[row]) * 0.125f;
}

// ---------------- P2: qk[h][d] = sum_{j<64} qs[h*64+j] * Wk[h*64+j][d] ----------------
// (score bias bk cancels in softmax normalization)
__global__ __launch_bounds__(256) void prologue_qk(const float* __restrict__ ipw) {
    int h = blockIdx.x;                 // 4 blocks
    __shared__ float qsl[64];
    int t = threadIdx.x;
    if (t < 64) qsl[t] = qsG[h * 64 + t];
    __syncthreads();
    const float* W = ipw + (size_t)(DIM + h * 64) * DIM;
    float a = 0.f;
#pragma unroll 16
    for (int j = 0; j < 64; j++) a += qsl[j] * W[j * DIM + t];
    qkGf[t * 4 + h] = a;
}

// ---------------- main: quarter-segment softmax-weighted sums, register scores -------
// No max subtraction (scores ~N(0,1): exp safe; max/bias cancel in normalization).
__global__ __launch_bounds__(256, 2) void seg_kernel(const float* __restrict__ X,
                                                     const int* __restrict__ seg, int N) {
    __shared__ __align__(16) float Xs[CHUNK * PITCH];  // 33.3 KB
    __shared__ float4 sp4[CHUNK][4];                   // lane-group score partials
    __shared__ float4 es4[CHUNK];
    __shared__ float4 dsm[32];
    __shared__ int segLoHi[2];

    int t = threadIdx.x, w = t >> 5, l = t & 31;
    int bid = blockIdx.x;
    int b = bid >> 2, quar = bid & 3;

    // thread-resident qk: heads-float4 per dim, dims 4l..4l+3 (lo) and 4(l+32)... (hi)
    const float4* Q4 = (const float4*)qkGf;
    float4 qlo[4], qhi[4];
#pragma unroll
    for (int c = 0; c < 4; c++) { qlo[c] = Q4[4 * l + c]; qhi[c] = Q4[128 + 4 * l + c]; }

    if (t == 0) {
        int lo = 0, hi = N;
        while (lo < hi) { int mid = (lo + hi) >> 1; if (seg[mid] < b) lo = mid + 1; else hi = mid; }
        int lo2 = lo, hi2 = N;
        while (lo2 < hi2) { int mid = (lo2 + hi2) >> 1; if (seg[mid] < b + 1) lo2 = mid + 1; else hi2 = mid; }
        int cnt = hi2 - lo;
        segLoHi[0] = lo + (cnt * quar) / NSPLIT;
        segLoHi[1] = lo + (cnt * (quar + 1)) / NSPLIT;
    }
    __syncthreads();

    float4 acc  = make_float4(0.f, 0.f, 0.f, 0.f);
    float4 dacc = make_float4(0.f, 0.f, 0.f, 0.f);
    int lo = segLoHi[0], hi = segLoHi[1];

    const float4* Xg = (const float4*)X;
    float4 R[4][2];
    int base = lo;
    int C = (hi > lo) ? min(CHUNK, hi - lo) : 0;
    if (C > 0) {
#pragma unroll
        for (int j = 0; j < 4; j++) {
            int n = w + 8 * j;
            if (n < C) {
                R[j][0] = Xg[(size_t)(base + n) * 64 + l];
                R[j][1] = Xg[(size_t)(base + n) * 64 + 32 + l];
            }
        }
    }

    while (base < hi) {
        // ---- STS chunk (row-linear, coalesced/conflict-free) ----
#pragma unroll
        for (int j = 0; j < 4; j++) {
            int n = w + 8 * j;
            if (n < C) {
                *(float4*)(Xs + n * PITCH + 4 * l)        = R[j][0];
                *(float4*)(Xs + n * PITCH + 4 * (l + 32)) = R[j][1];
            }
        }
        // ---- register score partials (no smem reads) ----
        float4 ps[4];
#pragma unroll
        for (int j = 0; j < 4; j++) {
            float4 a = R[j][0], c4 = R[j][1];
            float4 s;
            s.x = a.x * qlo[0].x + a.y * qlo[1].x + a.z * qlo[2].x + a.w * qlo[3].x
                + c4.x * qhi[0].x + c4.y * qhi[1].x + c4.z * qhi[2].x + c4.w * qhi[3].x;
            s.y = a.x * qlo[0].y + a.y * qlo[1].y + a.z * qlo[2].y + a.w * qlo[3].y
                + c4.x * qhi[0].y + c4.y * qhi[1].y + c4.z * qhi[2].y + c4.w * qhi[3].y;
            s.z = a.x * qlo[0].z + a.y * qlo[1].z + a.z * qlo[2].z + a.w * qlo[3].z
                + c4.x * qhi[0].z + c4.y * qhi[1].z + c4.z * qhi[2].z + c4.w * qhi[3].z;
            s.w = a.x * qlo[0].w + a.y * qlo[1].w + a.z * qlo[2].w + a.w * qlo[3].w
                + c4.x * qhi[0].w + c4.y * qhi[1].w + c4.z * qhi[2].w + c4.w * qhi[3].w;
            ps[j] = s;
        }
        // ---- prefetch next chunk ----
        int baseN = base + CHUNK;
        int CN = 0;
        if (baseN < hi) {
            CN = min(CHUNK, hi - baseN);
#pragma unroll
            for (int j = 0; j < 4; j++) {
                int n = w + 8 * j;
                if (n < CN) {
                    R[j][0] = Xg[(size_t)(baseN + n) * 64 + l];
                    R[j][1] = Xg[(size_t)(baseN + n) * 64 + 32 + l];
                }
            }
        }
        // ---- 3-round butterfly: lane l holds sum over lanes = l (mod 4) ----
#pragma unroll
        for (int j = 0; j < 4; j++) {
#pragma unroll
            for (int off = 16; off >= 4; off >>= 1) {
                ps[j].x += __shfl_xor_sync(0xffffffffu, ps[j].x, off);
                ps[j].y += __shfl_xor_sync(0xffffffffu, ps[j].y, off);
                ps[j].z += __shfl_xor_sync(0xffffffffu, ps[j].z, off);
                ps[j].w += __shfl_xor_sync(0xffffffffu, ps[j].w, off);
            }
        }
        if (l < 4) {
#pragma unroll
            for (int j = 0; j < 4; j++) sp4[w + 8 * j][l] = ps[j];
        }
        __syncwarp();
        if (l < 4) {   // lane l finishes node w+8l
            int n = w + 8 * l;
            float4 s0 = sp4[n][0], s1 = sp4[n][1], s2 = sp4[n][2], s3 = sp4[n][3];
            float4 e;
            if (n < C) {
                e.x = __expf(s0.x + s1.x + s2.x + s3.x);
                e.y = __expf(s0.y + s1.y + s2.y + s3.y);
                e.z = __expf(s0.z + s1.z + s2.z + s3.z);
                e.w = __expf(s0.w + s1.w + s2.w + s3.w);
                dacc.x += e.x; dacc.y += e.y; dacc.z += e.z; dacc.w += e.w;
            } else {
                e = make_float4(0.f, 0.f, 0.f, 0.f);
            }
            es4[n] = e;
        }
        __syncthreads();   // Xs + es4 ready

        // ---- rank-C update: acc[h] += e[n][h] * X[n][d=t] ----
        for (int n = 0; n < C; n++) {
            float4 e4 = es4[n];          // broadcast
            float xv = Xs[n * PITCH + t];
            acc.x += e4.x * xv;
            acc.y += e4.y * xv;
            acc.z += e4.z * xv;
            acc.w += e4.w * xv;
        }
        __syncthreads();   // protect Xs/es4 before next STS

        base = baseN;
        C = CN;
    }

    // ---- outputs: raw partial sums ----
    float* Ap = accPartG + (size_t)bid * 1024;
    Ap[0 * DIM + t] = acc.x;
    Ap[1 * DIM + t] = acc.y;
    Ap[2 * DIM + t] = acc.z;
    Ap[3 * DIM + t] = acc.w;
    // denom: lanes l<4 of each warp hold partials -> warp0 reduces all 32
    if (l < 4) dsm[w * 4 + l] = dacc;
    __syncthreads();
    if (w == 0) {
        float4 s = dsm[l];
#pragma unroll
        for (int off = 16; off; off >>= 1) {
            s.x += __shfl_xor_sync(0xffffffffu, s.x, off);
            s.y += __shfl_xor_sync(0xffffffffu, s.y, off);
            s.z += __shfl_xor_sync(0xffffffffu, s.z, off);
            s.w += __shfl_xor_sync(0xffffffffu, s.w, off);
        }
        if (l == 0) *(float4*)(denomPartG + bid * 4) = s;
    }
}

// ---------------- tiny GEMM: BM=8, BN=32, full K=256 in one SMEM phase ---------------
// mode 0: pooled = (sum of 4 quarter-partials, head-sliced)/denom @ Wv^T + bv
// mode 1: attn   = pooled @ Wo^T + opb
// mode 2: out    = attn @ Ww^T + ob  -> d_out
__global__ __launch_bounds__(256) void gemm_kernel(int mode,
                                                   const float* __restrict__ Wt,
                                                   const float* __restrict__ bias,
                                                   float* __restrict__ outp,
                                                   int Ncols) {
    __shared__ __align__(16) float As[8 * PITCH];
    __shared__ __align__(16) float Ws[32 * PITCH];
    int t = threadIdx.x;
    int r = t >> 5, c = t & 31;
    int nBase = blockIdx.x * 32, mBase = blockIdx.y * 8;

    if (mode == 0) {
        int hOff4 = (nBase >> 6) * 64;
#pragma unroll
        for (int i = 0; i < 2; i++) {
            int f = t + (i << 8);
            int m = f >> 6, k4 = f & 63;
            const float4* p0 = (const float4*)accPartG + (size_t)(mBase + m) * 1024 + hOff4 + k4;
            float4 a0 = p0[0], a1 = p0[256], a2 = p0[512], a3 = p0[768];
            float4 s = make_float4(a0.x + a1.x + a2.x + a3.x,
                                   a0.y + a1.y + a2.y + a3.y,
                                   a0.z + a1.z + a2.z + a3.z,
                                   a0.w + a1.w + a2.w + a3.w);
            *(float4*)(As + m * PITCH + 4 * k4) = s;
        }
    } else {
        const float* A = (mode == 1) ? pooledG : attnG;
#pragma unroll
        for (int i = 0; i < 2; i++) {
            int f = t + (i << 8);
            int m = f >> 6, k4 = f & 63;
            float4 a = ((const float4*)A)[(size_t)(mBase + m) * 64 + k4];
            *(float4*)(As + m * PITCH + 4 * k4) = a;
        }
    }
#pragma unroll
    for (int i = 0; i < 8; i++) {
        int f = t + (i << 8);
        int n = f >> 6, k4 = f & 63;
        float4 wv = ((const float4*)Wt)[(size_t)(nBase + n) * 64 + k4];
        *(float4*)(Ws + n * PITCH + 4 * k4) = wv;
    }
    __syncthreads();

    float acc = 0.f;
#pragma unroll
    for (int k4 = 0; k4 < 64; k4++) {
        float4 a4 = *(const float4*)(As + r * PITCH + 4 * k4);
        float4 w4 = *(const float4*)(Ws + c * PITCH + 4 * k4);
        acc += a4.x * w4.x + a4.y * w4.y + a4.z * w4.z + a4.w * w4.w;
    }

    int row = mBase + r, col = nBase + c;
    if (mode == 0) {
        int h = nBase >> 6;
        float d = denomPartG[(row * 4 + 0) * 4 + h] + denomPartG[(row * 4 + 1) * 4 + h]
                + denomPartG[(row * 4 + 2) * 4 + h] + denomPartG[(row * 4 + 3) * 4 + h];
        float inv = d > 0.f ? 1.f / d : 0.f;
        pooledG[row * DIM + col] = acc * inv + bias[col];
    } else if (mode == 1) {
        attnG[row * DIM + col] = acc + bias[col];
    } else {
        outp[(size_t)row * Ncols + col] = acc + bias[col];
    }
}

// ---------------- launch -------------------------------------------------------------
extern "C" void kernel_launch(void* const* d_in, const int* in_sizes, int n_in,
                              void* d_out, int out_size) {
    const float* node_feat = (const float*)d_in[0];
    const int*   segids    = (const int*)d_in[1];
    const float* gq        = (const float*)d_in[2];
    const float* ipw       = (const float*)d_in[3];
    const float* ipb       = (const float*)d_in[4];
    const float* opw       = (const float*)d_in[5];
    const float* opb       = (const float*)d_in[6];
    const float* ow        = (const float*)d_in[7];
    const float* ob        = (const float*)d_in[8];
    int N = in_sizes[0] / DIM;
    float* out = (float*)d_out;

    prologue_q<<<32, 256>>>(ipw, ipb, gq);
    prologue_qk<<<4, 256>>>(ipw);
    seg_kernel<<<NSPLIT * BSEG, 256>>>(node_feat, segids, N);
    gemm_kernel<<<dim3(8, 32), 256>>>(0, ipw + 512 * 256, ipb + 512, out, 256);
    gemm_kernel<<<dim3(8, 32), 256>>>(1, opw, opb, out, 256);
    gemm_kernel<<<dim3(16, 32), 256>>>(2, ow, ob, out, 512);
}

// round 8
// speedup vs baseline: 2.0789x; 1.3462x over previous
#include <cuda_runtime.h>
#include <float.h>

#define DIM    256
#define BSEG   256
#define NSPLIT 4
#define CHUNK  32
#define PITCH  260   // floats per SMEM row; conflict-free LDS patterns

// ---------------- scratch (static device arrays; no cudaMalloc) ----------------
__device__ int   segStartG[BSEG + 1];             // precomputed segment boundaries
__device__ float qsG[DIM];                        // scaled q
__device__ float qkGf[4 * DIM];                   // final qk, [d][h] interleaved
__device__ float accPartG[NSPLIT * BSEG * 1024];  // raw per-quarter sums, [b*4+q][h*256+d]
__device__ float denomPartG[NSPLIT * BSEG * 4];   // raw per-quarter denoms, [b*4+q][h]
__device__ float pooledG[BSEG * DIM];
__device__ float attnG[BSEG * DIM];

// ---------------- P0: segment boundaries (sorted ids -> start offsets) ----------------
__global__ __launch_bounds__(256) void seg_bounds(const int* __restrict__ seg, int N) {
    int i = blockIdx.x * 256 + threadIdx.x;
    if (i >= N) return;
    int s = seg[i];
    if (i == 0) {
        for (int b = 0; b <= s; b++) segStartG[b] = 0;
    } else {
        int p = seg[i - 1];
        if (p != s)
            for (int b = p + 1; b <= s; b++) segStartG[b] = i;
    }
    if (i == N - 1)
        for (int b = s + 1; b <= BSEG; b++) segStartG[b] = N;
}

// ---------------- P1: q = ((gq @ Wq^T) + bq) * (1/sqrt(64)) ----------------
__global__ __launch_bounds__(256) void prologue_q(const float* __restrict__ ipw,
                                                  const float* __restrict__ ipb,
                                                  const float* __restrict__ gq) {
    __shared__ float gqs[DIM];
    int t = threadIdx.x;
    gqs[t] = gq[t];
    __syncthreads();
    int w = t >> 5, l = t & 31;
    int row = blockIdx.x * 8 + w;
    float sum = 0.f;
#pragma unroll
    for (int k = l; k < DIM; k += 32) sum += ipw[row * DIM + k] * gqs[k];
#pragma unroll
    for (int off = 16; off; off >>= 1) sum += __shfl_xor_sync(0xffffffffu, sum, off);
    if (l == 0) qsG[row] = (sum + ipb[row]) * 0.125f;
}

// ---------------- P2: qk[h][d] = sum_{j<64} qs[h*64+j] * Wk[h*64+j][d] ----------------
// (score bias bk cancels in softmax normalization)
__global__ __launch_bounds__(256) void prologue_qk(const float* __restrict__ ipw) {
    int h = blockIdx.x;                 // 4 blocks
    __shared__ float qsl[64];
    int t = threadIdx.x;
    if (t < 64) qsl[t] = qsG[h * 64 + t];
    __syncthreads();
    const float* W = ipw + (size_t)(DIM + h * 64) * DIM;
    float a = 0.f;
#pragma unroll 16
    for (int j = 0; j < 64; j++) a += qsl[j] * W[j * DIM + t];
    qkGf[t * 4 + h] = a;
}

// ---------------- main: quarter-segment softmax-weighted sums, register scores -------
// No max subtraction (scores ~N(0,1): exp safe; max/bias cancel in normalization).
__global__ __launch_bounds__(256, 2) void seg_kernel(const float* __restrict__ X) {
    __shared__ __align__(16) float Xs[CHUNK * PITCH];  // 33.3 KB
    __shared__ float4 sp4[CHUNK][4];                   // lane-group score partials
    __shared__ float4 es4[CHUNK];
    __shared__ float4 dsm[32];

    int t = threadIdx.x, w = t >> 5, l = t & 31;
    int bid = blockIdx.x;
    int b = bid >> 2, quar = bid & 3;

    // thread-resident qk: heads-float4 per dim, dims 4l..4l+3 (lo) and 4(l+32)... (hi)
    const float4* Q4 = (const float4*)qkGf;
    float4 qlo[4], qhi[4];
#pragma unroll
    for (int c = 0; c < 4; c++) { qlo[c] = Q4[4 * l + c]; qhi[c] = Q4[128 + 4 * l + c]; }

    // boundaries: broadcast loads, no barrier needed
    int sLo = segStartG[b], sHi = segStartG[b + 1];
    int cnt = sHi - sLo;
    int lo = sLo + (cnt * quar) / NSPLIT;
    int hi = sLo + (cnt * (quar + 1)) / NSPLIT;

    float4 acc  = make_float4(0.f, 0.f, 0.f, 0.f);
    float4 dacc = make_float4(0.f, 0.f, 0.f, 0.f);

    const float4* Xg = (const float4*)X;
    float4 R[4][2];
    int base = lo;
    int C = (hi > lo) ? min(CHUNK, hi - lo) : 0;
    if (C > 0) {
#pragma unroll
        for (int j = 0; j < 4; j++) {
            int n = w + 8 * j;
            if (n < C) {
                R[j][0] = Xg[(size_t)(base + n) * 64 + l];
                R[j][1] = Xg[(size_t)(base + n) * 64 + 32 + l];
            }
        }
    }

    while (base < hi) {
        // ---- STS chunk (row-linear, coalesced/conflict-free) ----
#pragma unroll
        for (int j = 0; j < 4; j++) {
            int n = w + 8 * j;
            if (n < C) {
                *(float4*)(Xs + n * PITCH + 4 * l)        = R[j][0];
                *(float4*)(Xs + n * PITCH + 4 * (l + 32)) = R[j][1];
            }
        }
        // ---- register score partials (no smem reads) ----
        float4 ps[4];
#pragma unroll
        for (int j = 0; j < 4; j++) {
            float4 a = R[j][0], c4 = R[j][1];
            float4 s;
            s.x = a.x * qlo[0].x + a.y * qlo[1].x + a.z * qlo[2].x + a.w * qlo[3].x
                + c4.x * qhi[0].x + c4.y * qhi[1].x + c4.z * qhi[2].x + c4.w * qhi[3].x;
            s.y = a.x * qlo[0].y + a.y * qlo[1].y + a.z * qlo[2].y + a.w * qlo[3].y
                + c4.x * qhi[0].y + c4.y * qhi[1].y + c4.z * qhi[2].y + c4.w * qhi[3].y;
            s.z = a.x * qlo[0].z + a.y * qlo[1].z + a.z * qlo[2].z + a.w * qlo[3].z
                + c4.x * qhi[0].z + c4.y * qhi[1].z + c4.z * qhi[2].z + c4.w * qhi[3].z;
            s.w = a.x * qlo[0].w + a.y * qlo[1].w + a.z * qlo[2].w + a.w * qlo[3].w
                + c4.x * qhi[0].w + c4.y * qhi[1].w + c4.z * qhi[2].w + c4.w * qhi[3].w;
            ps[j] = s;
        }
        // ---- prefetch next chunk ----
        int baseN = base + CHUNK;
        int CN = 0;
        if (baseN < hi) {
            CN = min(CHUNK, hi - baseN);
#pragma unroll
            for (int j = 0; j < 4; j++) {
                int n = w + 8 * j;
                if (n < CN) {
                    R[j][0] = Xg[(size_t)(baseN + n) * 64 + l];
                    R[j][1] = Xg[(size_t)(baseN + n) * 64 + 32 + l];
                }
            }
        }
        // ---- 3-round butterfly: lane l holds sum over lanes = l (mod 4) ----
#pragma unroll
        for (int j = 0; j < 4; j++) {
#pragma unroll
            for (int off = 16; off >= 4; off >>= 1) {
                ps[j].x += __shfl_xor_sync(0xffffffffu, ps[j].x, off);
                ps[j].y += __shfl_xor_sync(0xffffffffu, ps[j].y, off);
                ps[j].z += __shfl_xor_sync(0xffffffffu, ps[j].z, off);
                ps[j].w += __shfl_xor_sync(0xffffffffu, ps[j].w, off);
            }
        }
        if (l < 4) {
#pragma unroll
            for (int j = 0; j < 4; j++) sp4[w + 8 * j][l] = ps[j];
        }
        __syncwarp();
        if (l < 4) {   // lane l finishes node w+8l
            int n = w + 8 * l;
            float4 s0 = sp4[n][0], s1 = sp4[n][1], s2 = sp4[n][2], s3 = sp4[n][3];
            float4 e;
            if (n < C) {
                e.x = __expf(s0.x + s1.x + s2.x + s3.x);
                e.y = __expf(s0.y + s1.y + s2.y + s3.y);
                e.z = __expf(s0.z + s1.z + s2.z + s3.z);
                e.w = __expf(s0.w + s1.w + s2.w + s3.w);
                dacc.x += e.x; dacc.y += e.y; dacc.z += e.z; dacc.w += e.w;
            } else {
                e = make_float4(0.f, 0.f, 0.f, 0.f);
            }
            es4[n] = e;
        }
        __syncthreads();   // Xs + es4 ready

        // ---- rank-C update: acc[h] += e[n][h] * X[n][d=t] ----
        for (int n = 0; n < C; n++) {
            float4 e4 = es4[n];          // broadcast
            float xv = Xs[n * PITCH + t];
            acc.x += e4.x * xv;
            acc.y += e4.y * xv;
            acc.z += e4.z * xv;
            acc.w += e4.w * xv;
        }
        __syncthreads();   // protect Xs/es4 before next STS

        base = baseN;
        C = CN;
    }

    // ---- outputs: raw partial sums ----
    float* Ap = accPartG + (size_t)bid * 1024;
    Ap[0 * DIM + t] = acc.x;
    Ap[1 * DIM + t] = acc.y;
    Ap[2 * DIM + t] = acc.z;
    Ap[3 * DIM + t] = acc.w;
    // denom: lanes l<4 of each warp hold partials -> warp0 reduces all 32
    if (l < 4) dsm[w * 4 + l] = dacc;
    __syncthreads();
    if (w == 0) {
        float4 s = dsm[l];
#pragma unroll
        for (int off = 16; off; off >>= 1) {
            s.x += __shfl_xor_sync(0xffffffffu, s.x, off);
            s.y += __shfl_xor_sync(0xffffffffu, s.y, off);
            s.z += __shfl_xor_sync(0xffffffffu, s.z, off);
            s.w += __shfl_xor_sync(0xffffffffu, s.w, off);
        }
        if (l == 0) *(float4*)(denomPartG + bid * 4) = s;
    }
}

// ---------------- tiny GEMM: BM=8, BN=32, full K=256 in one SMEM phase ---------------
// mode 0: pooled = (sum of 4 quarter-partials, head-sliced)/denom @ Wv^T + bv
// mode 1: attn   = pooled @ Wo^T + opb
// mode 2: out    = attn @ Ww^T + ob  -> d_out
__global__ __launch_bounds__(256) void gemm_kernel(int mode,
                                                   const float* __restrict__ Wt,
                                                   const float* __restrict__ bias,
                                                   float* __restrict__ outp,
                                                   int Ncols) {
    __shared__ __align__(16) float As[8 * PITCH];
    __shared__ __align__(16) float Ws[32 * PITCH];
    int t = threadIdx.x;
    int r = t >> 5, c = t & 31;
    int nBase = blockIdx.x * 32, mBase = blockIdx.y * 8;

    if (mode == 0) {
        int hOff4 = (nBase >> 6) * 64;
#pragma unroll
        for (int i = 0; i < 2; i++) {
            int f = t + (i << 8);
            int m = f >> 6, k4 = f & 63;
            const float4* p0 = (const float4*)accPartG + (size_t)(mBase + m) * 1024 + hOff4 + k4;
            float4 a0 = p0[0], a1 = p0[256], a2 = p0[512], a3 = p0[768];
            float4 s = make_float4(a0.x + a1.x + a2.x + a3.x,
                                   a0.y + a1.y + a2.y + a3.y,
                                   a0.z + a1.z + a2.z + a3.z,
                                   a0.w + a1.w + a2.w + a3.w);
            *(float4*)(As + m * PITCH + 4 * k4) = s;
        }
    } else {
        const float* A = (mode == 1) ? pooledG : attnG;
#pragma unroll
        for (int i = 0; i < 2; i++) {
            int f = t + (i << 8);
            int m = f >> 6, k4 = f & 63;
            float4 a = ((const float4*)A)[(size_t)(mBase + m) * 64 + k4];
            *(float4*)(As + m * PITCH + 4 * k4) = a;
        }
    }
#pragma unroll
    for (int i = 0; i < 8; i++) {
        int f = t + (i << 8);
        int n = f >> 6, k4 = f & 63;
        float4 wv = ((const float4*)Wt)[(size_t)(nBase + n) * 64 + k4];
        *(float4*)(Ws + n * PITCH + 4 * k4) = wv;
    }
    __syncthreads();

    float acc = 0.f;
#pragma unroll
    for (int k4 = 0; k4 < 64; k4++) {
        float4 a4 = *(const float4*)(As + r * PITCH + 4 * k4);
        float4 w4 = *(const float4*)(Ws + c * PITCH + 4 * k4);
        acc += a4.x * w4.x + a4.y * w4.y + a4.z * w4.z + a4.w * w4.w;
    }

    int row = mBase + r, col = nBase + c;
    if (mode == 0) {
        int h = nBase >> 6;
        float d = denomPartG[(row * 4 + 0) * 4 + h] + denomPartG[(row * 4 + 1) * 4 + h]
                + denomPartG[(row * 4 + 2) * 4 + h] + denomPartG[(row * 4 + 3) * 4 + h];
        float inv = d > 0.f ? 1.f / d : 0.f;
        pooledG[row * DIM + col] = acc * inv + bias[col];
    } else if (mode == 1) {
        attnG[row * DIM + col] = acc + bias[col];
    } else {
        outp[(size_t)row * Ncols + col] = acc + bias[col];
    }
}

// ---------------- launch (R7 resubmit: R6 design unchanged; broker infra error) -------
extern "C" void kernel_launch(void* const* d_in, const int* in_sizes, int n_in,
                              void* d_out, int out_size) {
    const float* node_feat = (const float*)d_in[0];
    const int*   segids    = (const int*)d_in[1];
    const float* gq        = (const float*)d_in[2];
    const float* ipw       = (const float*)d_in[3];
    const float* ipb       = (const float*)d_in[4];
    const float* opw       = (const float*)d_in[5];
    const float* opb       = (const float*)d_in[6];
    const float* ow        = (const float*)d_in[7];
    const float* ob        = (const float*)d_in[8];
    int N = in_sizes[0] / DIM;
    float* out = (float*)d_out;

    seg_bounds<<<(N + 255) / 256, 256>>>(segids, N);
    prologue_q<<<32, 256>>>(ipw, ipb, gq);
    prologue_qk<<<4, 256>>>(ipw);
    seg_kernel<<<NSPLIT * BSEG, 256>>>(node_feat);
    gemm_kernel<<<dim3(8, 32), 256>>>(0, ipw + 512 * 256, ipb + 512, out, 256);
    gemm_kernel<<<dim3(8, 32), 256>>>(1, opw, opb, out, 256);
    gemm_kernel<<<dim3(16, 32), 256>>>(2, ow, ob, out, 512);
}